// round 14
// baseline (speedup 1.0000x reference)
#include <cuda_runtime.h>
#include <cuda_fp16.h>
#include <cstdint>

#define B_ 2048
#define T_ 32
#define K_ 1024
#define D_ 256
#define BM 64
#define BN 32

// ---------------------------------------------------------------------------
// Scratch (static device arrays; no allocations allowed)
// ---------------------------------------------------------------------------
__device__ float  g_csq[T_ * K_];                // 0.5*||c||^2 (fp32 exact)
__device__ int    g_idx[B_ * T_];                // argmin indices
__device__ __half g_ch[(size_t)T_ * K_ * D_];    // codebook hi (fp16)
__device__ __half g_cl[(size_t)T_ * K_ * D_];    // codebook residual * 2048

// ---------------------------------------------------------------------------
// SMEM layout (bytes). Rows 264 halfs = 528B; 132 words == 4 (mod 32):
// ldmatrix 8-row matrices are bank-conflict-free.
// BM=64/BN=32 tiles -> 106.5KB/CTA -> 2 CTAs/SM (16 warps/SM latency hiding).
// ---------------------------------------------------------------------------
#define ASTR    528
#define AH_OFF  0
#define AL_OFF  33792       // 64*528
#define BH_OFF  67584
#define BL_OFF  84480       // +32*528
#define CSQ_OFF 101376      // 1024 floats
#define REDV_OFF 105472     // float sRedV[64][2]
#define REDI_OFF 105984     // int   sRedI[64][2]
#define SMEM_SZ  106496

__device__ __forceinline__ uint32_t smem_u32(const void* p) {
    uint32_t a;
    asm("{ .reg .u64 t; cvta.to.shared.u64 t, %1; cvt.u32.u64 %0, t; }" : "=r"(a) : "l"(p));
    return a;
}
__device__ __forceinline__ void ldsm4(uint32_t& r0, uint32_t& r1, uint32_t& r2,
                                      uint32_t& r3, uint32_t addr) {
    asm volatile("ldmatrix.sync.aligned.m8n8.x4.shared.b16 {%0,%1,%2,%3}, [%4];"
                 : "=r"(r0), "=r"(r1), "=r"(r2), "=r"(r3) : "r"(addr));
}
__device__ __forceinline__ void mma16816(float* c, const uint32_t* a, const uint32_t* b) {
    asm volatile("mma.sync.aligned.m16n8k16.row.col.f32.f16.f16.f32 "
                 "{%0,%1,%2,%3}, {%4,%5,%6,%7}, {%8,%9}, {%0,%1,%2,%3};"
                 : "+f"(c[0]), "+f"(c[1]), "+f"(c[2]), "+f"(c[3])
                 : "r"(a[0]), "r"(a[1]), "r"(a[2]), "r"(a[3]), "r"(b[0]), "r"(b[1]));
}
#define CP_ASYNC16(dst, src) \
    asm volatile("cp.async.cg.shared.global [%0], [%1], 16;" :: "r"(dst), "l"(src))
#define CP_COMMIT() asm volatile("cp.async.commit_group;")
#define CP_WAIT0()  asm volatile("cp.async.wait_group 0;")

// ---------------------------------------------------------------------------
// Kernel 1: codebook split (fp16 hi + 2048*residual) + 0.5*||c||^2. Warp/row.
// ---------------------------------------------------------------------------
__global__ void split_kernel(const float* __restrict__ cb) {
    int row  = blockIdx.x * 8 + (threadIdx.x >> 5);
    int lane = threadIdx.x & 31;
    const float4* p = (const float4*)(cb + (size_t)row * D_);
    float4 v0 = p[lane * 2 + 0];
    float4 v1 = p[lane * 2 + 1];
    float a[8] = {v0.x, v0.y, v0.z, v0.w, v1.x, v1.y, v1.z, v1.w};
    float s = 0.f;
#pragma unroll
    for (int i = 0; i < 8; i++) s += a[i] * a[i];
#pragma unroll
    for (int o = 16; o > 0; o >>= 1) s += __shfl_xor_sync(0xffffffffu, s, o);
    if (lane == 0) g_csq[row] = 0.5f * s;

    __half h[8], l[8];
#pragma unroll
    for (int i = 0; i < 8; i++) {
        h[i] = __float2half_rn(a[i]);
        l[i] = __float2half_rn((a[i] - __half2float(h[i])) * 2048.f);
    }
    uint4 uh, ul;
    uh.x = ((uint32_t)__half_as_ushort(h[0])) | ((uint32_t)__half_as_ushort(h[1]) << 16);
    uh.y = ((uint32_t)__half_as_ushort(h[2])) | ((uint32_t)__half_as_ushort(h[3]) << 16);
    uh.z = ((uint32_t)__half_as_ushort(h[4])) | ((uint32_t)__half_as_ushort(h[5]) << 16);
    uh.w = ((uint32_t)__half_as_ushort(h[6])) | ((uint32_t)__half_as_ushort(h[7]) << 16);
    ul.x = ((uint32_t)__half_as_ushort(l[0])) | ((uint32_t)__half_as_ushort(l[1]) << 16);
    ul.y = ((uint32_t)__half_as_ushort(l[2])) | ((uint32_t)__half_as_ushort(l[3]) << 16);
    ul.z = ((uint32_t)__half_as_ushort(l[4])) | ((uint32_t)__half_as_ushort(l[5]) << 16);
    ul.w = ((uint32_t)__half_as_ushort(l[6])) | ((uint32_t)__half_as_ushort(l[7]) << 16);
    *(uint4*)(g_ch + (size_t)row * D_ + lane * 8) = uh;
    *(uint4*)(g_cl + (size_t)row * D_ + lane * 8) = ul;
}

// ---------------------------------------------------------------------------
// Kernel 2: HMMA split-fp16 GEMM + fused argmin, 3-MMA form, ldmatrix loads,
// BM=64/BN=32 tiles at 2 CTAs/SM. 8 warps: 4 row-blocks(16) x 2 col-halves(16).
// ---------------------------------------------------------------------------
__global__ __launch_bounds__(256, 2)
void mma_kernel(const float* __restrict__ x) {
    extern __shared__ char smem[];
    const int tid  = threadIdx.x;
    const int lane = tid & 31;
    const int wid  = tid >> 5;
    const int t    = blockIdx.y;
    const int bm0  = blockIdx.x * BM;
    const int wm   = (wid >> 1) * 16;   // warp row offset (0,16,32,48)
    const int wn   = (wid & 1) * 16;    // warp col offset in 32-wide n-tile
    const int g    = lane >> 2;
    const int tig  = lane & 3;
    const uint32_t sb = smem_u32(smem);
    float* sCsq  = (float*)(smem + CSQ_OFF);
    float* sRedV = (float*)(smem + REDV_OFF);
    int*   sRedI = (int*)(smem + REDI_OFF);

    // ---- Prologue: stage x tile split to (hi, lo*2048) fp16; preload csq --
#pragma unroll
    for (int it = 0; it < 16; it++) {
        int q   = tid + it * 256;          // 4096 float4 loads (64 rows)
        int row = q >> 6;
        int c4  = q & 63;
        float4 v = *(const float4*)(x + ((size_t)(bm0 + row) * T_ + t) * D_ + c4 * 4);
        float a4[4] = {v.x, v.y, v.z, v.w};
        __half h4[4], l4[4];
#pragma unroll
        for (int i = 0; i < 4; i++) {
            h4[i] = __float2half_rn(a4[i]);
            l4[i] = __float2half_rn((a4[i] - __half2float(h4[i])) * 2048.f);
        }
        uint2 uh, ul;
        uh.x = ((uint32_t)__half_as_ushort(h4[0])) | ((uint32_t)__half_as_ushort(h4[1]) << 16);
        uh.y = ((uint32_t)__half_as_ushort(h4[2])) | ((uint32_t)__half_as_ushort(h4[3]) << 16);
        ul.x = ((uint32_t)__half_as_ushort(l4[0])) | ((uint32_t)__half_as_ushort(l4[1]) << 16);
        ul.y = ((uint32_t)__half_as_ushort(l4[2])) | ((uint32_t)__half_as_ushort(l4[3]) << 16);
        *(uint2*)(smem + AH_OFF + row * ASTR + c4 * 8) = uh;
        *(uint2*)(smem + AL_OFF + row * ASTR + c4 * 8) = ul;
    }
#pragma unroll
    for (int i = 0; i < 4; i++) sCsq[tid + i * 256] = g_csq[t * K_ + tid + i * 256];

    // ldmatrix per-lane base offsets.
    // A x4: lanes 0-15 -> rows wm+0..15 @kk; 16-31 -> same rows @kk+8
    const uint32_t aOff = (uint32_t)(wm + (lane & 15)) * ASTR + ((uint32_t)(lane >> 4) << 4);
    // B x4: (oct0@k, oct0@k+8, oct1@k, oct1@k+8) for cols wn..wn+15
    const uint32_t bOff = (uint32_t)(wn + (lane & 7) + ((lane >> 4) << 3)) * ASTR
                        + (((uint32_t)(lane >> 3) & 1) << 4);

    float best[2];
    int   bidx[2];
#pragma unroll
    for (int i = 0; i < 2; i++) { best[i] = 3.4e38f; bidx[i] = 0; }

    const float inv = 1.f / 2048.f;

    for (int nt = 0; nt < K_ / BN; nt++) {
        const int n0 = nt * BN;
        __syncthreads();   // prev k-loop done (B reuse) / prologue done (nt=0)

        // ---- cp.async B tile: 32 codes x 256 d, hi + lo (2048 uint4) ----
#pragma unroll
        for (int it = 0; it < 8; it++) {
            int q   = tid + it * 256;
            int arr = q >> 10;
            int e   = q & 1023;
            int n   = e >> 5;
            int ck  = e & 31;
            const __half* src = (arr ? g_cl : g_ch)
                              + ((size_t)t * K_ + n0 + n) * D_ + ck * 8;
            uint32_t dst = sb + (arr ? BL_OFF : BH_OFF) + n * ASTR + ck * 16;
            CP_ASYNC16(dst, src);
        }
        CP_COMMIT();
        CP_WAIT0();
        __syncthreads();

        // ---- K-loop: C1 = xh*ch ; C2 = xh*cl + xl*ch ----
        float C1[2][4], C2[2][4];
#pragma unroll
        for (int nb = 0; nb < 2; nb++)
#pragma unroll
            for (int r = 0; r < 4; r++) { C1[nb][r] = 0.f; C2[nb][r] = 0.f; }

#pragma unroll 2
        for (int kk = 0; kk < D_; kk += 16) {
            uint32_t ah[4], al[4], bh[2][2], bl[2][2];
            uint32_t a = aOff + (uint32_t)kk * 2;
            ldsm4(ah[0], ah[1], ah[2], ah[3], sb + AH_OFF + a);
            ldsm4(al[0], al[1], al[2], al[3], sb + AL_OFF + a);
            uint32_t b = bOff + (uint32_t)kk * 2;
            ldsm4(bh[0][0], bh[0][1], bh[1][0], bh[1][1], sb + BH_OFF + b);
            ldsm4(bl[0][0], bl[0][1], bl[1][0], bl[1][1], sb + BL_OFF + b);
#pragma unroll
            for (int nb = 0; nb < 2; nb++) {
                mma16816(C1[nb], ah, bh[nb]);
                mma16816(C2[nb], ah, bl[nb]);
                mma16816(C2[nb], al, bh[nb]);
            }
        }

        // ---- Fused argmin over this tile ----
        // C frag: c0:(g,c) c1:(g,c+1) c2:(g+8,c) c3:(g+8,c+1), c = tig*2.
#pragma unroll
        for (int nb = 0; nb < 2; nb++) {
            int gcol = n0 + wn + nb * 8 + tig * 2;
            float cs0 = sCsq[gcol];
            float cs1 = sCsq[gcol + 1];
            float s0 = cs0 - (C1[nb][0] + C2[nb][0] * inv);
            float s1 = cs1 - (C1[nb][1] + C2[nb][1] * inv);
            float s2 = cs0 - (C1[nb][2] + C2[nb][2] * inv);
            float s3 = cs1 - (C1[nb][3] + C2[nb][3] * inv);
            if (s0 < best[0]) { best[0] = s0; bidx[0] = gcol; }
            if (s1 < best[0]) { best[0] = s1; bidx[0] = gcol + 1; }
            if (s2 < best[1]) { best[1] = s2; bidx[1] = gcol; }
            if (s3 < best[1]) { best[1] = s3; bidx[1] = gcol + 1; }
        }
    }

    // ---- Quad reduction (tig lanes hold different cols of same rows) ----
#pragma unroll
    for (int i = 0; i < 2; i++) {
#pragma unroll
        for (int off = 1; off <= 2; off <<= 1) {
            float v  = __shfl_xor_sync(0xffffffffu, best[i], off);
            int   ix = __shfl_xor_sync(0xffffffffu, bidx[i], off);
            if (v < best[i] || (v == best[i] && ix < bidx[i])) {
                best[i] = v; bidx[i] = ix;
            }
        }
    }

    // ---- Cross-warp combine: the 2 col-half warps of each row block ----
    if (tig == 0) {
        int half = wn >> 4;   // 0 or 1
#pragma unroll
        for (int h = 0; h < 2; h++) {
            int r = wm + h * 8 + g;
            sRedV[r * 2 + half] = best[h];
            sRedI[r * 2 + half] = bidx[h];
        }
    }
    __syncthreads();
    if (tid < BM) {
        float v0 = sRedV[tid * 2],     v1 = sRedV[tid * 2 + 1];
        int   i0 = sRedI[tid * 2],     i1 = sRedI[tid * 2 + 1];
        int   win = (v1 < v0 || (v1 == v0 && i1 < i0)) ? i1 : i0;
        g_idx[(size_t)(bm0 + tid) * T_ + t] = win;
    }
}

// ---------------------------------------------------------------------------
// Kernel 3: gather winning codebook rows; append idxes (as float) if present.
// ---------------------------------------------------------------------------
__global__ void gather_kernel(const float* __restrict__ cb,
                              float* __restrict__ out, int write_idx) {
    int bt  = blockIdx.x;
    int t   = bt & (T_ - 1);
    int idx = g_idx[bt];
    const float4* src = (const float4*)(cb + ((size_t)t * K_ + idx) * D_);
    float4*       dst = (float4*)(out + (size_t)bt * D_);
    dst[threadIdx.x] = src[threadIdx.x];
    if (write_idx && threadIdx.x == 0)
        out[(size_t)B_ * T_ * D_ + bt] = (float)idx;
}

// ---------------------------------------------------------------------------
extern "C" void kernel_launch(void* const* d_in, const int* in_sizes, int n_in,
                              void* d_out, int out_size) {
    const float* x  = (const float*)d_in[0];   // [B, T, D] fp32
    const float* cb = (const float*)d_in[1];   // [T, K, D] fp32
    float* out = (float*)d_out;

    split_kernel<<<(T_ * K_) / 8, 256>>>(cb);

    cudaFuncSetAttribute(mma_kernel, cudaFuncAttributeMaxDynamicSharedMemorySize, SMEM_SZ);
    dim3 grid(B_ / BM, T_);
    mma_kernel<<<grid, 256, SMEM_SZ>>>(x);

    int write_idx = (out_size >= B_ * T_ * D_ + B_ * T_) ? 1 : 0;
    gather_kernel<<<B_ * T_, 64>>>(cb, out, write_idx);
}

// round 15
// speedup vs baseline: 1.4522x; 1.4522x over previous
#include <cuda_runtime.h>
#include <cuda_fp16.h>
#include <cstdint>

#define B_ 2048
#define T_ 32
#define K_ 1024
#define D_ 256
#define BM 128
#define MARGIN 0.5f

// ---------------------------------------------------------------------------
// Scratch (static device arrays; no allocations allowed)
// ---------------------------------------------------------------------------
__device__ float  g_csq[T_ * K_];                // 0.5*||c||^2 (fp32 exact)
__device__ int    g_idx[B_ * T_];                // argmin indices
__device__ __half g_ch[(size_t)T_ * K_ * D_];    // codebook hi (fp16)
__device__ int    g_nres;                        // # ambiguous rows
__device__ int    g_resrow[B_ * T_];             // ambiguous row ids
__device__ int    g_rescnt[B_ * T_];             // candidate count (0 => full scan)
__device__ int    g_rescand[(size_t)B_ * T_ * 8];

// ---------------------------------------------------------------------------
// SMEM layout (bytes). A/B rows 264 halfs = 528B; 132 words == 4 (mod 32):
// ldmatrix 8-row matrices are bank-conflict-free.
// ---------------------------------------------------------------------------
#define ASTR    528
#define AH_OFF  0           // 128*528 = 67584
#define BH_OFF  67584       // 64*528  = 33792
#define CSQ_OFF 101376      // 1024 floats
#define CV1_OFF 105472      // float [128][8]
#define CI1_OFF 109568      // int   [128][8]
#define CV2_OFF 113664      // float [128][8]
#define CI2_OFF 117760      // int   [128][8]
#define SMEM_SZ 121856

__device__ __forceinline__ uint32_t smem_u32(const void* p) {
    uint32_t a;
    asm("{ .reg .u64 t; cvta.to.shared.u64 t, %1; cvt.u32.u64 %0, t; }" : "=r"(a) : "l"(p));
    return a;
}
__device__ __forceinline__ void ldsm4(uint32_t& r0, uint32_t& r1, uint32_t& r2,
                                      uint32_t& r3, uint32_t addr) {
    asm volatile("ldmatrix.sync.aligned.m8n8.x4.shared.b16 {%0,%1,%2,%3}, [%4];"
                 : "=r"(r0), "=r"(r1), "=r"(r2), "=r"(r3) : "r"(addr));
}
__device__ __forceinline__ void mma16816(float* c, const uint32_t* a, const uint32_t* b) {
    asm volatile("mma.sync.aligned.m16n8k16.row.col.f32.f16.f16.f32 "
                 "{%0,%1,%2,%3}, {%4,%5,%6,%7}, {%8,%9}, {%0,%1,%2,%3};"
                 : "+f"(c[0]), "+f"(c[1]), "+f"(c[2]), "+f"(c[3])
                 : "r"(a[0]), "r"(a[1]), "r"(a[2]), "r"(a[3]), "r"(b[0]), "r"(b[1]));
}

// ---------------------------------------------------------------------------
// Kernel 1: codebook -> fp16 hi + 0.5*||c||^2 (fp32). One warp per row.
// Also zeroes the resolve counter.
// ---------------------------------------------------------------------------
__global__ void split_kernel(const float* __restrict__ cb) {
    if (blockIdx.x == 0 && threadIdx.x == 0) g_nres = 0;
    int row  = blockIdx.x * 8 + (threadIdx.x >> 5);
    int lane = threadIdx.x & 31;
    const float4* p = (const float4*)(cb + (size_t)row * D_);
    float4 v0 = p[lane * 2 + 0];
    float4 v1 = p[lane * 2 + 1];
    float a[8] = {v0.x, v0.y, v0.z, v0.w, v1.x, v1.y, v1.z, v1.w};
    float s = 0.f;
#pragma unroll
    for (int i = 0; i < 8; i++) s += a[i] * a[i];
#pragma unroll
    for (int o = 16; o > 0; o >>= 1) s += __shfl_xor_sync(0xffffffffu, s, o);
    if (lane == 0) g_csq[row] = 0.5f * s;

    __half h[8];
#pragma unroll
    for (int i = 0; i < 8; i++) h[i] = __float2half_rn(a[i]);
    uint4 uh;
    uh.x = ((uint32_t)__half_as_ushort(h[0])) | ((uint32_t)__half_as_ushort(h[1]) << 16);
    uh.y = ((uint32_t)__half_as_ushort(h[2])) | ((uint32_t)__half_as_ushort(h[3]) << 16);
    uh.z = ((uint32_t)__half_as_ushort(h[4])) | ((uint32_t)__half_as_ushort(h[5]) << 16);
    uh.w = ((uint32_t)__half_as_ushort(h[6])) | ((uint32_t)__half_as_ushort(h[7]) << 16);
    *(uint4*)(g_ch + (size_t)row * D_ + lane * 8) = uh;
}

// ---------------------------------------------------------------------------
// Kernel 2: hi-only HMMA screen + per-thread top-2 + margin test.
// R13 geometry: grid (B/128, T), 256 threads = 8 warps (4x2), warp tile 32x32.
// Safe rows write g_idx directly; ambiguous rows (gap <= MARGIN) enqueue
// their in-margin candidates for exact resolve.
// ---------------------------------------------------------------------------
__global__ __launch_bounds__(256, 1)
void screen_kernel(const float* __restrict__ x) {
    extern __shared__ char smem[];
    const int tid  = threadIdx.x;
    const int lane = tid & 31;
    const int wid  = tid >> 5;
    const int t    = blockIdx.y;
    const int bm0  = blockIdx.x * BM;
    const int wm   = (wid >> 1) * 32;
    const int wn   = (wid & 1) * 32;
    const int g    = lane >> 2;
    const int tig  = lane & 3;
    const uint32_t sb = smem_u32(smem);
    float* sCsq = (float*)(smem + CSQ_OFF);
    float* sV1  = (float*)(smem + CV1_OFF);
    int*   sI1  = (int*)(smem + CI1_OFF);
    float* sV2  = (float*)(smem + CV2_OFF);
    int*   sI2  = (int*)(smem + CI2_OFF);

    // ---- Prologue: stage x tile as fp16 hi; preload csq ----
#pragma unroll
    for (int it = 0; it < 16; it++) {
        int q   = tid + it * 256;          // 4096 float4 covering 128 rows? (128*64)
        int row = q >> 6;
        int c4  = q & 63;
        // two passes of rows: q in [0,4096) covers rows 0..63; second half below
        float4 v = *(const float4*)(x + ((size_t)(bm0 + row) * T_ + t) * D_ + c4 * 4);
        __half h4[4] = {__float2half_rn(v.x), __float2half_rn(v.y),
                        __float2half_rn(v.z), __float2half_rn(v.w)};
        uint2 uh;
        uh.x = ((uint32_t)__half_as_ushort(h4[0])) | ((uint32_t)__half_as_ushort(h4[1]) << 16);
        uh.y = ((uint32_t)__half_as_ushort(h4[2])) | ((uint32_t)__half_as_ushort(h4[3]) << 16);
        *(uint2*)(smem + AH_OFF + row * ASTR + c4 * 8) = uh;
    }
#pragma unroll
    for (int it = 16; it < 32; it++) {     // rows 64..127
        int q   = tid + it * 256;
        int row = q >> 6;
        int c4  = q & 63;
        float4 v = *(const float4*)(x + ((size_t)(bm0 + row) * T_ + t) * D_ + c4 * 4);
        __half h4[4] = {__float2half_rn(v.x), __float2half_rn(v.y),
                        __float2half_rn(v.z), __float2half_rn(v.w)};
        uint2 uh;
        uh.x = ((uint32_t)__half_as_ushort(h4[0])) | ((uint32_t)__half_as_ushort(h4[1]) << 16);
        uh.y = ((uint32_t)__half_as_ushort(h4[2])) | ((uint32_t)__half_as_ushort(h4[3]) << 16);
        *(uint2*)(smem + AH_OFF + row * ASTR + c4 * 8) = uh;
    }
#pragma unroll
    for (int i = 0; i < 4; i++) sCsq[tid + i * 256] = g_csq[t * K_ + tid + i * 256];

    const uint32_t aOff = (uint32_t)(wm + (lane & 15)) * ASTR + ((uint32_t)(lane >> 4) << 4);
    const uint32_t bOff = (uint32_t)(wn + (lane & 7) + ((lane >> 4) << 3)) * ASTR
                        + (((uint32_t)(lane >> 3) & 1) << 4);

    // Per-thread top-2 per row-slot (4 slots: mb*2 + row-half)
    float b1[4], b2[4];
    int   i1[4], i2[4];
#pragma unroll
    for (int i = 0; i < 4; i++) { b1[i] = 3.4e38f; b2[i] = 3.4e38f; i1[i] = 0; i2[i] = 0; }

    for (int nt = 0; nt < 16; nt++) {
        const int n0 = nt * 64;
        __syncthreads();

        // ---- Load B tile (hi only): 64 codes x 256 d = 2048 uint4 ----
#pragma unroll
        for (int it = 0; it < 8; it++) {
            int q  = tid + it * 256;
            int n  = q >> 5;
            int ck = q & 31;
            const __half* src = g_ch + ((size_t)t * K_ + n0 + n) * D_ + ck * 8;
            *(uint4*)(smem + BH_OFF + n * ASTR + ck * 16) = *(const uint4*)src;
        }
        __syncthreads();

        float C1[2][4][4];
#pragma unroll
        for (int mb = 0; mb < 2; mb++)
#pragma unroll
            for (int nb = 0; nb < 4; nb++)
#pragma unroll
                for (int r = 0; r < 4; r++) C1[mb][nb][r] = 0.f;

#pragma unroll 2
        for (int kk = 0; kk < D_; kk += 16) {
            uint32_t ah[2][4], bh[4][2];
#pragma unroll
            for (int mb = 0; mb < 2; mb++) {
                uint32_t a = aOff + (uint32_t)mb * (16 * ASTR) + (uint32_t)kk * 2;
                ldsm4(ah[mb][0], ah[mb][1], ah[mb][2], ah[mb][3], sb + AH_OFF + a);
            }
#pragma unroll
            for (int nb2 = 0; nb2 < 2; nb2++) {
                uint32_t b = bOff + (uint32_t)nb2 * (16 * ASTR) + (uint32_t)kk * 2;
                ldsm4(bh[nb2*2][0], bh[nb2*2][1], bh[nb2*2+1][0], bh[nb2*2+1][1],
                      sb + BH_OFF + b);
            }
#pragma unroll
            for (int mb = 0; mb < 2; mb++)
#pragma unroll
                for (int nb = 0; nb < 4; nb++)
                    mma16816(C1[mb][nb], ah[mb], bh[nb]);
        }

        // ---- Top-2 update. Slots: u = mb*2 + (frag row-half). ----
#pragma unroll
        for (int nb = 0; nb < 4; nb++) {
            int gcol = n0 + wn + nb * 8 + tig * 2;
            float cs0 = sCsq[gcol];
            float cs1 = sCsq[gcol + 1];
#pragma unroll
            for (int mb = 0; mb < 2; mb++) {
                float s0 = cs0 - C1[mb][nb][0];
                float s1 = cs1 - C1[mb][nb][1];
                float s2 = cs0 - C1[mb][nb][2];
                float s3 = cs1 - C1[mb][nb][3];
                int u = mb * 2;
                if (s0 < b1[u]) { b2[u]=b1[u]; i2[u]=i1[u]; b1[u]=s0; i1[u]=gcol; }
                else if (s0 < b2[u]) { b2[u]=s0; i2[u]=gcol; }
                if (s1 < b1[u]) { b2[u]=b1[u]; i2[u]=i1[u]; b1[u]=s1; i1[u]=gcol+1; }
                else if (s1 < b2[u]) { b2[u]=s1; i2[u]=gcol+1; }
                u++;
                if (s2 < b1[u]) { b2[u]=b1[u]; i2[u]=i1[u]; b1[u]=s2; i1[u]=gcol; }
                else if (s2 < b2[u]) { b2[u]=s2; i2[u]=gcol; }
                if (s3 < b1[u]) { b2[u]=b1[u]; i2[u]=i1[u]; b1[u]=s3; i1[u]=gcol+1; }
                else if (s3 < b2[u]) { b2[u]=s3; i2[u]=gcol+1; }
            }
        }
    }

    // ---- Dump per-thread top-2 to SMEM: 8 owner threads per row ----
    __syncthreads();   // B region done; candidate arrays are separate anyway
    {
        int col8 = (wn >> 5) * 4 + tig;   // 0..7
#pragma unroll
        for (int mb = 0; mb < 2; mb++)
#pragma unroll
            for (int h = 0; h < 2; h++) {
                int row = wm + mb * 16 + h * 8 + g;
                int u = mb * 2 + h;
                sV1[row * 8 + col8] = b1[u];  sI1[row * 8 + col8] = i1[u];
                sV2[row * 8 + col8] = b2[u];  sI2[row * 8 + col8] = i2[u];
            }
    }
    __syncthreads();

    // ---- Per-row margin test (threads 0..127) ----
    if (tid < BM) {
        int row = tid;
        float m1 = 3.4e38f; int mi = 0x7fffffff; int mj = -1;
#pragma unroll
        for (int j = 0; j < 8; j++) {
            float v = sV1[row * 8 + j]; int i = sI1[row * 8 + j];
            if (v < m1 || (v == m1 && i < mi)) { m1 = v; mi = i; mj = j; }
        }
        float m2 = 3.4e38f;
#pragma unroll
        for (int j = 0; j < 8; j++) {
            float v1 = sV1[row * 8 + j];
            if (j != mj && v1 < m2) m2 = v1;
            float v2 = sV2[row * 8 + j];
            if (v2 < m2) m2 = v2;
        }
        int rowid = (bm0 + row) * T_ + t;
        if (m2 - m1 > MARGIN) {
            g_idx[rowid] = mi;
        } else {
            float thr = m1 + MARGIN;
            int cand[8]; int cnt = 0; int ovf = 0;
#pragma unroll
            for (int j = 0; j < 8; j++) {
                if (sV1[row * 8 + j] <= thr) {
                    if (cnt < 8) cand[cnt++] = sI1[row * 8 + j]; else ovf = 1;
                }
                if (sV2[row * 8 + j] <= thr) {
                    if (cnt < 8) cand[cnt++] = sI2[row * 8 + j]; else ovf = 1;
                }
            }
            int slot = atomicAdd(&g_nres, 1);
            g_resrow[slot] = rowid;
            g_rescnt[slot] = ovf ? 0 : cnt;
            for (int c = 0; c < cnt; c++) g_rescand[(size_t)slot * 8 + c] = cand[c];
        }
    }
}

// ---------------------------------------------------------------------------
// Kernel 3: exact fp32 resolve for ambiguous rows. One warp per entry.
// cnt==0 => full 1024-code scan (overflow fallback; ~never).
// ---------------------------------------------------------------------------
__global__ void resolve_kernel(const float* __restrict__ x,
                               const float* __restrict__ cb) {
    int lane = threadIdx.x & 31;
    int e0   = blockIdx.x * 4 + (threadIdx.x >> 5);
    int n    = g_nres;
    for (int e = e0; e < n; e += gridDim.x * 4) {
        int rowid = g_resrow[e];
        int t = rowid & (T_ - 1);
        const float* xr = x + (size_t)rowid * D_;
        float xv[8];
#pragma unroll
        for (int u = 0; u < 8; u++) xv[u] = xr[lane + u * 32];
        int cnt = g_rescnt[e];
        float best = 3.4e38f; int bi = 0x7fffffff;
        int lo = 0, hi = cnt;
        int full = (cnt == 0);
        if (full) { lo = 0; hi = K_; }
        for (int ci = lo; ci < hi; ci++) {
            int k = full ? ci : g_rescand[(size_t)e * 8 + ci];
            const float* cr = cb + ((size_t)t * K_ + k) * D_;
            float dot = 0.f, c2 = 0.f;
#pragma unroll
            for (int u = 0; u < 8; u++) {
                float cv = cr[lane + u * 32];
                dot += xv[u] * cv;
                c2  += cv * cv;
            }
#pragma unroll
            for (int o = 16; o > 0; o >>= 1) {
                dot += __shfl_xor_sync(0xffffffffu, dot, o);
                c2  += __shfl_xor_sync(0xffffffffu, c2, o);
            }
            float s = 0.5f * c2 - dot;
            if (s < best || (s == best && k < bi)) { best = s; bi = k; }
        }
        if (lane == 0) g_idx[rowid] = bi;
    }
}

// ---------------------------------------------------------------------------
// Kernel 4: gather winning codebook rows; append idxes (as float) if present.
// ---------------------------------------------------------------------------
__global__ void gather_kernel(const float* __restrict__ cb,
                              float* __restrict__ out, int write_idx) {
    int bt  = blockIdx.x;
    int t   = bt & (T_ - 1);
    int idx = g_idx[bt];
    const float4* src = (const float4*)(cb + ((size_t)t * K_ + idx) * D_);
    float4*       dst = (float4*)(out + (size_t)bt * D_);
    dst[threadIdx.x] = src[threadIdx.x];
    if (write_idx && threadIdx.x == 0)
        out[(size_t)B_ * T_ * D_ + bt] = (float)idx;
}

// ---------------------------------------------------------------------------
extern "C" void kernel_launch(void* const* d_in, const int* in_sizes, int n_in,
                              void* d_out, int out_size) {
    const float* x  = (const float*)d_in[0];   // [B, T, D] fp32
    const float* cb = (const float*)d_in[1];   // [T, K, D] fp32
    float* out = (float*)d_out;

    split_kernel<<<(T_ * K_) / 8, 256>>>(cb);

    cudaFuncSetAttribute(screen_kernel, cudaFuncAttributeMaxDynamicSharedMemorySize, SMEM_SZ);
    dim3 grid(B_ / BM, T_);
    screen_kernel<<<grid, 256, SMEM_SZ>>>(x);

    resolve_kernel<<<512, 128>>>(x, cb);

    int write_idx = (out_size >= B_ * T_ * D_ + B_ * T_) ? 1 : 0;
    gather_kernel<<<B_ * T_, 64>>>(cb, out, write_idx);
}